// round 5
// baseline (speedup 1.0000x reference)
#include <cuda_runtime.h>
#include <math.h>

// Problem constants
#define S_LEN   4096
#define H_DIM   4096
#define NQH     32
#define NKVH    8
#define HD      128
#define QKV_N   6144   // NQ*D + 2*NKV*D
#define ATTN_SCALE 0.08838834764831845f   // 128^-0.5
// -log2(10000)/64
#define NEG_L2T_OVER_64 (-0.20762050593046014f)

// Scratch (allocation-free rule: __device__ globals)
__device__ float g_qkv[(size_t)S_LEN * QKV_N];   // QKV with RoPE applied
__device__ float g_attn[(size_t)S_LEN * H_DIM];  // attention output pre-Wo

// ---------------------------------------------------------------------------
// SGEMM: C[M,N] = A[M,K] @ B[K,N], all row-major. 128x128 tile, BK=8,
// 256 threads, 8x8 per-thread fragment split as (0..3, 64..67) in both dims.
// If ROPE: column tile == one head (N tile width 128 == D); apply RoPE in
// registers for head tiles < NQH+NKVH (q and k regions), pass-through for v.
// ---------------------------------------------------------------------------
template<bool ROPE>
__global__ __launch_bounds__(256)
void sgemm128(const float* __restrict__ A, const float* __restrict__ B,
              float* __restrict__ C, int M, int N, int K,
              const int* __restrict__ positions)
{
    __shared__ float As[8][128];   // [k][m]
    __shared__ float Bs[8][128];   // [k][n]

    const int tid = threadIdx.x;
    const int tx = tid & 15;
    const int ty = tid >> 4;
    const int m0 = blockIdx.y * 128;
    const int n0 = blockIdx.x * 128;

    // global load mapping
    const int a_r = m0 + (tid >> 1);      // A row
    const int a_c = (tid & 1) * 4;        // A col within K-tile
    const int b_r = tid >> 5;             // B row within K-tile
    const int b_c = n0 + (tid & 31) * 4;  // B col

    float4 pa = *reinterpret_cast<const float4*>(&A[(size_t)a_r * K + a_c]);
    float4 pb = *reinterpret_cast<const float4*>(&B[(size_t)b_r * N + b_c]);

    float acc[8][8];
    #pragma unroll
    for (int i = 0; i < 8; i++)
        #pragma unroll
        for (int j = 0; j < 8; j++) acc[i][j] = 0.f;

    for (int k0 = 0; k0 < K; k0 += 8) {
        // stage prefetched tile into smem
        As[a_c + 0][tid >> 1] = pa.x;
        As[a_c + 1][tid >> 1] = pa.y;
        As[a_c + 2][tid >> 1] = pa.z;
        As[a_c + 3][tid >> 1] = pa.w;
        *reinterpret_cast<float4*>(&Bs[b_r][(tid & 31) * 4]) = pb;
        __syncthreads();

        // prefetch next tile into registers
        if (k0 + 8 < K) {
            pa = *reinterpret_cast<const float4*>(&A[(size_t)a_r * K + (k0 + 8 + a_c)]);
            pb = *reinterpret_cast<const float4*>(&B[(size_t)(k0 + 8 + b_r) * N + b_c]);
        }

        #pragma unroll
        for (int kk = 0; kk < 8; kk++) {
            float4 a0 = *reinterpret_cast<float4*>(&As[kk][ty * 4]);
            float4 a1 = *reinterpret_cast<float4*>(&As[kk][ty * 4 + 64]);
            float4 b0 = *reinterpret_cast<float4*>(&Bs[kk][tx * 4]);
            float4 b1 = *reinterpret_cast<float4*>(&Bs[kk][tx * 4 + 64]);
            float av[8] = {a0.x, a0.y, a0.z, a0.w, a1.x, a1.y, a1.z, a1.w};
            float bv[8] = {b0.x, b0.y, b0.z, b0.w, b1.x, b1.y, b1.z, b1.w};
            #pragma unroll
            for (int i = 0; i < 8; i++)
                #pragma unroll
                for (int j = 0; j < 8; j++)
                    acc[i][j] += av[i] * bv[j];
        }
        __syncthreads();
    }

    // RoPE in registers: fragment cols (tx*4+jj, 64+tx*4+jj) are exactly the
    // rotation pair (d, d+64) of this head. Heads 0..39 are Q/K; 40..47 are V.
    if (ROPE && blockIdx.x < (NQH + NKVH)) {
        #pragma unroll
        for (int ii = 0; ii < 8; ii++) {
            int r = m0 + ty * 4 + (ii & 3) + ((ii >> 2) << 6);
            float pos = (float)positions[r];
            #pragma unroll
            for (int jj = 0; jj < 4; jj++) {
                int d1 = tx * 4 + jj;                         // 0..63
                float inv = exp2f((float)d1 * NEG_L2T_OVER_64);
                float fr = pos * inv;
                float sn, cs;
                sincosf(fr, &sn, &cs);
                float x1 = acc[ii][jj];
                float x2 = acc[ii][jj + 4];
                acc[ii][jj]     = x1 * cs - x2 * sn;
                acc[ii][jj + 4] = x2 * cs + x1 * sn;
            }
        }
    }

    #pragma unroll
    for (int ii = 0; ii < 8; ii++) {
        int r = m0 + ty * 4 + (ii & 3) + ((ii >> 2) << 6);
        float4 c0 = make_float4(acc[ii][0], acc[ii][1], acc[ii][2], acc[ii][3]);
        float4 c1 = make_float4(acc[ii][4], acc[ii][5], acc[ii][6], acc[ii][7]);
        float* dst = &C[(size_t)r * N + n0 + tx * 4];
        *reinterpret_cast<float4*>(dst)      = c0;
        *reinterpret_cast<float4*>(dst + 64) = c1;
    }
}

// ---------------------------------------------------------------------------
// Flash attention: one block = 64 query rows of one q-head. Online softmax
// over causal key blocks of 64. 256 threads (16x16): score frag 4x4,
// O frag 4 rows x 8 cols. Q/K stored d-major in smem for conflict-free
// float4 fragment reads; P staged through smem for the PV GEMM.
// ---------------------------------------------------------------------------
#define QT_STRIDE 68
#define ATTN_SMEM_FLOATS (128*QT_STRIDE /*Qt*/ + 128*QT_STRIDE /*Kt*/ + 64*128 /*Vs*/ + 64*QT_STRIDE /*Ps*/)
#define ATTN_SMEM_BYTES (ATTN_SMEM_FLOATS * 4)

__global__ __launch_bounds__(256)
void attn_kernel(const float* __restrict__ qkv, float* __restrict__ aout)
{
    extern __shared__ float sm[];
    float* Qt = sm;                      // [128][68]  Qt[d][r]
    float* Kt = Qt + 128 * QT_STRIDE;    // [128][68]  Kt[d][c]
    float* Vs = Kt + 128 * QT_STRIDE;    // [64][128]  Vs[c][d]
    float* Ps = Vs + 64 * 128;           // [64][68]   Ps[r][c]

    const int tid = threadIdx.x;
    const int tx = tid & 15;
    const int ty = tid >> 4;
    const int qb = (int)gridDim.x - 1 - (int)blockIdx.x;  // big blocks first
    const int h = blockIdx.y;
    const int g = h >> 2;   // GRP = 4
    const int qrow0 = qb * 64;

    const float* Qg = qkv + (size_t)h * HD;
    const float* Kg = qkv + (size_t)NQH * HD + (size_t)g * HD;
    const float* Vg = qkv + (size_t)(NQH + NKVH) * HD + (size_t)g * HD;

    // Load Q tile (64 rows x 128 d), transposed into smem
    #pragma unroll
    for (int n = 0; n < 32; n++) {
        int e = n * 256 + tid;
        int d = e & 127, r = e >> 7;
        Qt[d * QT_STRIDE + r] = Qg[(size_t)(qrow0 + r) * QKV_N + d];
    }

    float m_i[4], l_i[4], o[4][8];
    #pragma unroll
    for (int i = 0; i < 4; i++) {
        m_i[i] = -1e30f; l_i[i] = 0.f;
        #pragma unroll
        for (int j = 0; j < 8; j++) o[i][j] = 0.f;
    }

    for (int kb = 0; kb <= qb; kb++) {
        // Load K tile (transposed) and V tile (row-major)
        #pragma unroll
        for (int n = 0; n < 32; n++) {
            int e = n * 256 + tid;
            int d = e & 127, r = e >> 7;
            Kt[d * QT_STRIDE + r] = Kg[(size_t)(kb * 64 + r) * QKV_N + d];
        }
        #pragma unroll
        for (int n = 0; n < 8; n++) {
            int f = n * 256 + tid;
            int d4 = f & 31, r = f >> 5;
            *reinterpret_cast<float4*>(&Vs[r * 128 + d4 * 4]) =
                *reinterpret_cast<const float4*>(&Vg[(size_t)(kb * 64 + r) * QKV_N + d4 * 4]);
        }
        __syncthreads();

        // scores = Q @ K^T (frag 4x4)
        float s[4][4];
        #pragma unroll
        for (int i = 0; i < 4; i++)
            #pragma unroll
            for (int j = 0; j < 4; j++) s[i][j] = 0.f;

        #pragma unroll 4
        for (int d = 0; d < 128; d++) {
            float4 a = *reinterpret_cast<float4*>(&Qt[d * QT_STRIDE + ty * 4]);
            float4 b = *reinterpret_cast<float4*>(&Kt[d * QT_STRIDE + tx * 4]);
            float av[4] = {a.x, a.y, a.z, a.w};
            float bv[4] = {b.x, b.y, b.z, b.w};
            #pragma unroll
            for (int i = 0; i < 4; i++)
                #pragma unroll
                for (int j = 0; j < 4; j++)
                    s[i][j] += av[i] * bv[j];
        }

        const bool diag = (kb == qb);
        #pragma unroll
        for (int i = 0; i < 4; i++) {
            int rg = qrow0 + ty * 4 + i;
            float mx = -1e30f;
            #pragma unroll
            for (int j = 0; j < 4; j++) {
                float v = s[i][j] * ATTN_SCALE;
                if (diag && (kb * 64 + tx * 4 + j) > rg) v = -1e30f;
                s[i][j] = v;
                mx = fmaxf(mx, v);
            }
            // reduce max over the 16 lanes that own this row
            #pragma unroll
            for (int off = 8; off > 0; off >>= 1)
                mx = fmaxf(mx, __shfl_xor_sync(0xffffffffu, mx, off));
            float mnew = fmaxf(m_i[i], mx);
            float alpha = __expf(m_i[i] - mnew);
            float ls = 0.f;
            #pragma unroll
            for (int j = 0; j < 4; j++) {
                s[i][j] = __expf(s[i][j] - mnew);
                ls += s[i][j];
            }
            #pragma unroll
            for (int off = 8; off > 0; off >>= 1)
                ls += __shfl_xor_sync(0xffffffffu, ls, off);
            l_i[i] = l_i[i] * alpha + ls;
            m_i[i] = mnew;
            #pragma unroll
            for (int j = 0; j < 8; j++) o[i][j] *= alpha;
            *reinterpret_cast<float4*>(&Ps[(ty * 4 + i) * QT_STRIDE + tx * 4]) =
                make_float4(s[i][0], s[i][1], s[i][2], s[i][3]);
        }
        __syncthreads();

        // O += P @ V
        #pragma unroll 2
        for (int c = 0; c < 64; c++) {
            float4 v0 = *reinterpret_cast<float4*>(&Vs[c * 128 + tx * 8]);
            float4 v1 = *reinterpret_cast<float4*>(&Vs[c * 128 + tx * 8 + 4]);
            float vv[8] = {v0.x, v0.y, v0.z, v0.w, v1.x, v1.y, v1.z, v1.w};
            #pragma unroll
            for (int i = 0; i < 4; i++) {
                float p = Ps[(ty * 4 + i) * QT_STRIDE + c];
                #pragma unroll
                for (int j = 0; j < 8; j++)
                    o[i][j] += p * vv[j];
            }
        }
        __syncthreads();   // before next iteration overwrites Kt/Vs
    }

    #pragma unroll
    for (int i = 0; i < 4; i++) {
        float inv = 1.f / l_i[i];
        int r = qrow0 + ty * 4 + i;
        float4 w0 = make_float4(o[i][0] * inv, o[i][1] * inv, o[i][2] * inv, o[i][3] * inv);
        float4 w1 = make_float4(o[i][4] * inv, o[i][5] * inv, o[i][6] * inv, o[i][7] * inv);
        float* dst = &aout[(size_t)r * H_DIM + h * HD + tx * 8];
        *reinterpret_cast<float4*>(dst)     = w0;
        *reinterpret_cast<float4*>(dst + 4) = w1;
    }
}

// ---------------------------------------------------------------------------
// Launch
// ---------------------------------------------------------------------------
extern "C" void kernel_launch(void* const* d_in, const int* in_sizes, int n_in,
                              void* d_out, int out_size)
{
    (void)in_sizes; (void)n_in; (void)out_size;
    const int*   positions = (const int*)d_in[0];
    const float* hidden    = (const float*)d_in[1];
    const float* w_qkv     = (const float*)d_in[2];
    const float* w_o       = (const float*)d_in[3];
    float* out = (float*)d_out;

    float *qkv_ptr = nullptr, *attn_ptr = nullptr;
    cudaGetSymbolAddress((void**)&qkv_ptr, g_qkv);
    cudaGetSymbolAddress((void**)&attn_ptr, g_attn);

    cudaFuncSetAttribute(attn_kernel,
                         cudaFuncAttributeMaxDynamicSharedMemorySize,
                         ATTN_SMEM_BYTES);

    // 1) QKV GEMM fused with RoPE epilogue
    sgemm128<true><<<dim3(QKV_N / 128, S_LEN / 128), 256>>>(
        hidden, w_qkv, qkv_ptr, S_LEN, QKV_N, H_DIM, positions);

    // 2) causal GQA flash attention
    attn_kernel<<<dim3(S_LEN / 64, NQH), 256, ATTN_SMEM_BYTES>>>(qkv_ptr, attn_ptr);

    // 3) output projection
    sgemm128<false><<<dim3(H_DIM / 128, S_LEN / 128), 256>>>(
        attn_ptr, w_o, out, S_LEN, H_DIM, H_DIM, nullptr);
}

// round 8
// speedup vs baseline: 1.5966x; 1.5966x over previous
#include <cuda_runtime.h>
#include <math.h>

// Problem constants
#define S_LEN   4096
#define H_DIM   4096
#define NQH     32
#define NKVH    8
#define HD      128
#define QKV_N   6144   // NQ*D + 2*NKV*D
#define ATTN_SCALE 0.08838834764831845f   // 128^-0.5
// -log2(10000)/64
#define NEG_L2T_OVER_64 (-0.20762050593046014f)

// Scratch (allocation-free rule: __device__ globals)
__device__ float g_qkv[(size_t)S_LEN * QKV_N];   // QKV with RoPE applied
__device__ float g_attn[(size_t)S_LEN * H_DIM];  // attention output pre-Wo

// ---------------------------------------------------------------------------
// SGEMM: C[M,N] = A[M,K] @ B[K,N], all row-major. 128x128 tile, BK=8,
// 256 threads, 8x8 per-thread fragment split as (0..3, 64..67) in both dims.
// If ROPE: column tile == one head (N tile width 128 == D); apply RoPE in
// registers for head tiles < NQH+NKVH (q and k regions), pass-through for v.
// ---------------------------------------------------------------------------
template<bool ROPE>
__global__ __launch_bounds__(256)
void sgemm128(const float* __restrict__ A, const float* __restrict__ B,
              float* __restrict__ C, int M, int N, int K,
              const int* __restrict__ positions)
{
    __shared__ float As[8][128];   // [k][m]
    __shared__ float Bs[8][128];   // [k][n]

    const int tid = threadIdx.x;
    const int tx = tid & 15;
    const int ty = tid >> 4;
    const int m0 = blockIdx.y * 128;
    const int n0 = blockIdx.x * 128;

    // global load mapping
    const int a_r = m0 + (tid >> 1);      // A row
    const int a_c = (tid & 1) * 4;        // A col within K-tile
    const int b_r = tid >> 5;             // B row within K-tile
    const int b_c = n0 + (tid & 31) * 4;  // B col

    float4 pa = *reinterpret_cast<const float4*>(&A[(size_t)a_r * K + a_c]);
    float4 pb = *reinterpret_cast<const float4*>(&B[(size_t)b_r * N + b_c]);

    float acc[8][8];
    #pragma unroll
    for (int i = 0; i < 8; i++)
        #pragma unroll
        for (int j = 0; j < 8; j++) acc[i][j] = 0.f;

    for (int k0 = 0; k0 < K; k0 += 8) {
        // stage prefetched tile into smem
        As[a_c + 0][tid >> 1] = pa.x;
        As[a_c + 1][tid >> 1] = pa.y;
        As[a_c + 2][tid >> 1] = pa.z;
        As[a_c + 3][tid >> 1] = pa.w;
        *reinterpret_cast<float4*>(&Bs[b_r][(tid & 31) * 4]) = pb;
        __syncthreads();

        // prefetch next tile into registers
        if (k0 + 8 < K) {
            pa = *reinterpret_cast<const float4*>(&A[(size_t)a_r * K + (k0 + 8 + a_c)]);
            pb = *reinterpret_cast<const float4*>(&B[(size_t)(k0 + 8 + b_r) * N + b_c]);
        }

        #pragma unroll
        for (int kk = 0; kk < 8; kk++) {
            float4 a0 = *reinterpret_cast<float4*>(&As[kk][ty * 4]);
            float4 a1 = *reinterpret_cast<float4*>(&As[kk][ty * 4 + 64]);
            float4 b0 = *reinterpret_cast<float4*>(&Bs[kk][tx * 4]);
            float4 b1 = *reinterpret_cast<float4*>(&Bs[kk][tx * 4 + 64]);
            float av[8] = {a0.x, a0.y, a0.z, a0.w, a1.x, a1.y, a1.z, a1.w};
            float bv[8] = {b0.x, b0.y, b0.z, b0.w, b1.x, b1.y, b1.z, b1.w};
            #pragma unroll
            for (int i = 0; i < 8; i++)
                #pragma unroll
                for (int j = 0; j < 8; j++)
                    acc[i][j] += av[i] * bv[j];
        }
        __syncthreads();
    }

    // RoPE in registers: fragment cols (tx*4+jj, 64+tx*4+jj) are exactly the
    // rotation pair (d, d+64) of this head. Heads 0..39 are Q/K; 40..47 are V.
    if (ROPE && blockIdx.x < (NQH + NKVH)) {
        #pragma unroll
        for (int ii = 0; ii < 8; ii++) {
            int r = m0 + ty * 4 + (ii & 3) + ((ii >> 2) << 6);
            float pos = (float)positions[r];
            #pragma unroll
            for (int jj = 0; jj < 4; jj++) {
                int d1 = tx * 4 + jj;                         // 0..63
                float inv = exp2f((float)d1 * NEG_L2T_OVER_64);
                float fr = pos * inv;
                float sn, cs;
                sincosf(fr, &sn, &cs);
                float x1 = acc[ii][jj];
                float x2 = acc[ii][jj + 4];
                acc[ii][jj]     = x1 * cs - x2 * sn;
                acc[ii][jj + 4] = x2 * cs + x1 * sn;
            }
        }
    }

    #pragma unroll
    for (int ii = 0; ii < 8; ii++) {
        int r = m0 + ty * 4 + (ii & 3) + ((ii >> 2) << 6);
        float4 c0 = make_float4(acc[ii][0], acc[ii][1], acc[ii][2], acc[ii][3]);
        float4 c1 = make_float4(acc[ii][4], acc[ii][5], acc[ii][6], acc[ii][7]);
        float* dst = &C[(size_t)r * N + n0 + tx * 4];
        *reinterpret_cast<float4*>(dst)      = c0;
        *reinterpret_cast<float4*>(dst + 64) = c1;
    }
}

// ---------------------------------------------------------------------------
// Flash attention: one block = 64 query rows of one q-head. Online softmax
// over causal key blocks of 64. 256 threads (16x16): score frag 4x4,
// O frag 4 rows x 8 cols. Q/K stored d-major in smem for conflict-free
// float4 fragment reads; P staged through smem for the PV GEMM.
// ---------------------------------------------------------------------------
#define QT_STRIDE 68
#define ATTN_SMEM_FLOATS (128*QT_STRIDE /*Qt*/ + 128*QT_STRIDE /*Kt*/ + 64*128 /*Vs*/ + 64*QT_STRIDE /*Ps*/)
#define ATTN_SMEM_BYTES (ATTN_SMEM_FLOATS * 4)

__global__ __launch_bounds__(256)
void attn_kernel(const float* __restrict__ qkv, float* __restrict__ aout)
{
    extern __shared__ float sm[];
    float* Qt = sm;                      // [128][68]  Qt[d][r]
    float* Kt = Qt + 128 * QT_STRIDE;    // [128][68]  Kt[d][c]
    float* Vs = Kt + 128 * QT_STRIDE;    // [64][128]  Vs[c][d]
    float* Ps = Vs + 64 * 128;           // [64][68]   Ps[r][c]

    const int tid = threadIdx.x;
    const int tx = tid & 15;
    const int ty = tid >> 4;
    const int qb = (int)gridDim.x - 1 - (int)blockIdx.x;  // big blocks first
    const int h = blockIdx.y;
    const int g = h >> 2;   // GRP = 4
    const int qrow0 = qb * 64;

    const float* Qg = qkv + (size_t)h * HD;
    const float* Kg = qkv + (size_t)NQH * HD + (size_t)g * HD;
    const float* Vg = qkv + (size_t)(NQH + NKVH) * HD + (size_t)g * HD;

    // Load Q tile (64 rows x 128 d), transposed into smem
    #pragma unroll
    for (int n = 0; n < 32; n++) {
        int e = n * 256 + tid;
        int d = e & 127, r = e >> 7;
        Qt[d * QT_STRIDE + r] = Qg[(size_t)(qrow0 + r) * QKV_N + d];
    }

    float m_i[4], l_i[4], o[4][8];
    #pragma unroll
    for (int i = 0; i < 4; i++) {
        m_i[i] = -1e30f; l_i[i] = 0.f;
        #pragma unroll
        for (int j = 0; j < 8; j++) o[i][j] = 0.f;
    }

    for (int kb = 0; kb <= qb; kb++) {
        // Load K tile (transposed) and V tile (row-major)
        #pragma unroll
        for (int n = 0; n < 32; n++) {
            int e = n * 256 + tid;
            int d = e & 127, r = e >> 7;
            Kt[d * QT_STRIDE + r] = Kg[(size_t)(kb * 64 + r) * QKV_N + d];
        }
        #pragma unroll
        for (int n = 0; n < 8; n++) {
            int f = n * 256 + tid;
            int d4 = f & 31, r = f >> 5;
            *reinterpret_cast<float4*>(&Vs[r * 128 + d4 * 4]) =
                *reinterpret_cast<const float4*>(&Vg[(size_t)(kb * 64 + r) * QKV_N + d4 * 4]);
        }
        __syncthreads();

        // scores = Q @ K^T (frag 4x4)
        float s[4][4];
        #pragma unroll
        for (int i = 0; i < 4; i++)
            #pragma unroll
            for (int j = 0; j < 4; j++) s[i][j] = 0.f;

        #pragma unroll 4
        for (int d = 0; d < 128; d++) {
            float4 a = *reinterpret_cast<float4*>(&Qt[d * QT_STRIDE + ty * 4]);
            float4 b = *reinterpret_cast<float4*>(&Kt[d * QT_STRIDE + tx * 4]);
            float av[4] = {a.x, a.y, a.z, a.w};
            float bv[4] = {b.x, b.y, b.z, b.w};
            #pragma unroll
            for (int i = 0; i < 4; i++)
                #pragma unroll
                for (int j = 0; j < 4; j++)
                    s[i][j] += av[i] * bv[j];
        }

        const bool diag = (kb == qb);
        #pragma unroll
        for (int i = 0; i < 4; i++) {
            int rg = qrow0 + ty * 4 + i;
            float mx = -1e30f;
            #pragma unroll
            for (int j = 0; j < 4; j++) {
                float v = s[i][j] * ATTN_SCALE;
                if (diag && (kb * 64 + tx * 4 + j) > rg) v = -1e30f;
                s[i][j] = v;
                mx = fmaxf(mx, v);
            }
            // reduce max over the 16 lanes that own this row
            #pragma unroll
            for (int off = 8; off > 0; off >>= 1)
                mx = fmaxf(mx, __shfl_xor_sync(0xffffffffu, mx, off));
            float mnew = fmaxf(m_i[i], mx);
            float alpha = __expf(m_i[i] - mnew);
            float ls = 0.f;
            #pragma unroll
            for (int j = 0; j < 4; j++) {
                s[i][j] = __expf(s[i][j] - mnew);
                ls += s[i][j];
            }
            #pragma unroll
            for (int off = 8; off > 0; off >>= 1)
                ls += __shfl_xor_sync(0xffffffffu, ls, off);
            l_i[i] = l_i[i] * alpha + ls;
            m_i[i] = mnew;
            #pragma unroll
            for (int j = 0; j < 8; j++) o[i][j] *= alpha;
            *reinterpret_cast<float4*>(&Ps[(ty * 4 + i) * QT_STRIDE + tx * 4]) =
                make_float4(s[i][0], s[i][1], s[i][2], s[i][3]);
        }
        __syncthreads();

        // O += P @ V
        #pragma unroll 2
        for (int c = 0; c < 64; c++) {
            float4 v0 = *reinterpret_cast<float4*>(&Vs[c * 128 + tx * 8]);
            float4 v1 = *reinterpret_cast<float4*>(&Vs[c * 128 + tx * 8 + 4]);
            float vv[8] = {v0.x, v0.y, v0.z, v0.w, v1.x, v1.y, v1.z, v1.w};
            #pragma unroll
            for (int i = 0; i < 4; i++) {
                float p = Ps[(ty * 4 + i) * QT_STRIDE + c];
                #pragma unroll
                for (int j = 0; j < 8; j++)
                    o[i][j] += p * vv[j];
            }
        }
        __syncthreads();   // before next iteration overwrites Kt/Vs
    }

    #pragma unroll
    for (int i = 0; i < 4; i++) {
        float inv = 1.f / l_i[i];
        int r = qrow0 + ty * 4 + i;
        float4 w0 = make_float4(o[i][0] * inv, o[i][1] * inv, o[i][2] * inv, o[i][3] * inv);
        float4 w1 = make_float4(o[i][4] * inv, o[i][5] * inv, o[i][6] * inv, o[i][7] * inv);
        float* dst = &aout[(size_t)r * H_DIM + h * HD + tx * 8];
        *reinterpret_cast<float4*>(dst)     = w0;
        *reinterpret_cast<float4*>(dst + 4) = w1;
    }
}

// ---------------------------------------------------------------------------
// Launch
// ---------------------------------------------------------------------------
extern "C" void kernel_launch(void* const* d_in, const int* in_sizes, int n_in,
                              void* d_out, int out_size)
{
    (void)in_sizes; (void)n_in; (void)out_size;
    const int*   positions = (const int*)d_in[0];
    const float* hidden    = (const float*)d_in[1];
    const float* w_qkv     = (const float*)d_in[2];
    const float* w_o       = (const float*)d_in[3];
    float* out = (float*)d_out;

    float *qkv_ptr = nullptr, *attn_ptr = nullptr;
    cudaGetSymbolAddress((void**)&qkv_ptr, g_qkv);
    cudaGetSymbolAddress((void**)&attn_ptr, g_attn);

    cudaFuncSetAttribute(attn_kernel,
                         cudaFuncAttributeMaxDynamicSharedMemorySize,
                         ATTN_SMEM_BYTES);

    // 1) QKV GEMM fused with RoPE epilogue
    sgemm128<true><<<dim3(QKV_N / 128, S_LEN / 128), 256>>>(
        hidden, w_qkv, qkv_ptr, S_LEN, QKV_N, H_DIM, positions);

    // 2) causal GQA flash attention
    attn_kernel<<<dim3(S_LEN / 64, NQH), 256, ATTN_SMEM_BYTES>>>(qkv_ptr, attn_ptr);

    // 3) output projection
    sgemm128<false><<<dim3(H_DIM / 128, S_LEN / 128), 256>>>(
        attn_ptr, w_o, out, S_LEN, H_DIM, H_DIM, nullptr);
}